// round 6
// baseline (speedup 1.0000x reference)
#include <cuda_runtime.h>
#include <cstdint>
#include <cstddef>

#define Bx 4
#define Vx 64
#define Ex 1024
#define Lx 1024
#define Dx 256

#define XSTR 260   // Xs/Zs row stride (floats)
#define WSTR 36    // Ws row stride
#define SSTR 68    // Ss row stride

__device__ float g_Mt[256 * 256];  // Mt[n][k] = (Wq^T Wk)[k][n], tf32-rounded
__device__ float g_u[256];         // u[k] = sum_c Wq[c][k]*bk[c]
__device__ float g_r[256];         // r[n] = sum_c bq[c]*Wk[c][n]
__device__ float g_c0;             // bq . bk

__device__ __forceinline__ float tf32r(float x) {
    unsigned u; asm("cvt.rna.tf32.f32 %0, %1;" : "=r"(u) : "f"(x));
    return __uint_as_float(u);
}

__device__ __forceinline__ void mma_tf32(float (&d)[4], const unsigned (&a)[4],
                                         unsigned b0, unsigned b1) {
    asm volatile("mma.sync.aligned.m16n8k8.row.col.f32.tf32.tf32.f32 "
                 "{%0,%1,%2,%3}, {%4,%5,%6,%7}, {%8,%9}, {%0,%1,%2,%3};"
                 : "+f"(d[0]), "+f"(d[1]), "+f"(d[2]), "+f"(d[3])
                 : "r"(a[0]), "r"(a[1]), "r"(a[2]), "r"(a[3]), "r"(b0), "r"(b1));
}

// ---------------- precompute ----------------
__global__ void precompute_kernel(const float* __restrict__ Wq, const float* __restrict__ bq,
                                  const float* __restrict__ Wk, const float* __restrict__ bk)
{
    __shared__ float sWk[256];
    __shared__ float red[256];
    const int n = blockIdx.x, j = threadIdx.x;
    sWk[j] = Wk[j * 256 + n];
    __syncthreads();
    float acc = 0.f, uacc = 0.f;
    #pragma unroll 4
    for (int d = 0; d < 256; d++) {
        float wq = Wq[d * 256 + j];
        acc = fmaf(wq, sWk[d], acc);
        if (n == 0) uacc = fmaf(wq, __ldg(bk + d), uacc);
    }
    g_Mt[n * 256 + j] = tf32r(acc);
    if (n == 0) g_u[j] = uacc;
    red[j] = bq[j] * sWk[j];
    __syncthreads();
    for (int s = 128; s > 0; s >>= 1) { if (j < s) red[j] += red[j + s]; __syncthreads(); }
    if (j == 0) g_r[n] = red[0];
    if (n == 0) {
        red[j] = bq[j] * __ldg(bk + j);
        __syncthreads();
        for (int s = 128; s > 0; s >>= 1) { if (j < s) red[j] += red[j + s]; __syncthreads(); }
        if (j == 0) g_c0 = red[0];
    }
}

// ---------------- main: one CTA per (b,l), 512 threads ----------------
__global__ __launch_bounds__(512, 1)
void edge_learner_main(const float* __restrict__ hs,
                       const int*   __restrict__ edge_index,
                       const float* __restrict__ edge_weight,
                       const float* __restrict__ attn_skip_p,
                       float* __restrict__ out)
{
    extern __shared__ float sm[];
    float* Xs  = sm;                     // 64*260
    float* Zs  = Xs + 64 * XSTR;         // 64*260
    float* Ws0 = Zs + 64 * XSTR;         // 256*36
    float* Ws1 = Ws0 + 256 * WSTR;       // 256*36
    float* Su  = Ws1 + 256 * WSTR;       // 256
    float* Sr  = Su + 256;               // 256
    float* Sa  = Sr + 256;               // 64
    float* Sc  = Sa + 64;                // 64
    int*   Sd  = (int*)(Sc + 64);        // 1024
    float* Sew = (float*)(Sd + 1024);    // 1024
    float* Zp  = Ws0;                    // overlay: GEMM1 k-half partials (64*260)
    float* Ssq = Ws0;                    // overlay: GEMM2 k-quarter partials (4 * 64*68)

    const int bx = blockIdx.x;
    const int b = bx >> 10, l = bx & 1023;
    const int t = threadIdx.x, w = t >> 5, j = t & 31;

    // prefetch W chunk 0 via cp.async
    {
        #pragma unroll
        for (int i = 0; i < 4; i++) {
            int idx = i * 512 + t, n = idx >> 3, q = idx & 7;
            unsigned d = (unsigned)__cvta_generic_to_shared(Ws0 + n * WSTR + q * 4);
            asm volatile("cp.async.ca.shared.global [%0], [%1], 16;"
                         :: "r"(d), "l"(g_Mt + n * 256 + q * 4));
        }
        asm volatile("cp.async.commit_group;" ::: "memory");
    }

    // ---- ei output fill ----
    {
        const int base = bx * 2048;
        #pragma unroll
        for (int r = 0; r < 4; r++) {
            int idx = base + r * 512 + t;
            out[idx] = (float)edge_index[idx >> 10];
        }
    }

    // ---- stage X = hs[b,:,l,:] (tf32-rounded) ----
    {
        const int k4 = t & 63, vo = t >> 6;
        #pragma unroll
        for (int it = 0; it < 8; it++) {
            int v = it * 8 + vo;
            float4 val = *(const float4*)(hs + (size_t)(b * Vx + v) * (Lx * Dx)
                                             + (size_t)l * Dx + k4 * 4);
            val.x = tf32r(val.x); val.y = tf32r(val.y);
            val.z = tf32r(val.z); val.w = tf32r(val.w);
            *(float4*)(Xs + v * XSTR + k4 * 4) = val;
        }
    }
    if (t < 256) { Su[t] = g_u[t]; Sr[t] = g_r[t]; }
    {
        const int*   dsts = edge_index + Bx * Ex + b * Ex;
        const float* ews  = edge_weight + b * Ex;
        #pragma unroll
        for (int i = 0; i < 2; i++) {
            Sd[i * 512 + t]  = dsts[i * 512 + t];
            Sew[i * 512 + t] = ews[i * 512 + t];
        }
    }
    __syncthreads();

    // ---- per-vertex bias dots: Sa[v] = X_v.u , Sc[v] = X_v.r ----
    {
        const float4 ua = ((const float4*)Su)[j];
        const float4 ub = ((const float4*)Su)[32 + j];
        const float4 ra = ((const float4*)Sr)[j];
        const float4 rb = ((const float4*)Sr)[32 + j];
        #pragma unroll
        for (int s4 = 0; s4 < 4; s4++) {
            int v = w * 4 + s4;
            float4 xa = *(const float4*)(Xs + v * XSTR + 4 * j);
            float4 xb = *(const float4*)(Xs + v * XSTR + 128 + 4 * j);
            float pa = xa.x*ua.x + xa.y*ua.y + xa.z*ua.z + xa.w*ua.w
                     + xb.x*ub.x + xb.y*ub.y + xb.z*ub.z + xb.w*ub.w;
            float pc = xa.x*ra.x + xa.y*ra.y + xa.z*ra.z + xa.w*ra.w
                     + xb.x*rb.x + xb.y*rb.y + xb.z*rb.z + xb.w*rb.w;
            #pragma unroll
            for (int off = 16; off > 0; off >>= 1) {
                pa += __shfl_xor_sync(~0u, pa, off);
                pc += __shfl_xor_sync(~0u, pc, off);
            }
            if (j == 0) { Sa[v] = pa; Sc[v] = pc; }
        }
    }

    // ---- GEMM 1: Z[64][256] = X @ Mt^T, 16 warps: (m2 x n4) x ks-half split ----
    const int rA = j >> 2, cA = j & 3;
    const int mb = (w & 1) * 32;
    const int nb = ((w >> 1) & 3) * 64;
    const int sH = w >> 3;                  // ks-half within each chunk
    {
        float acc[2][8][4];
        #pragma unroll
        for (int a = 0; a < 2; a++)
            #pragma unroll
            for (int c = 0; c < 8; c++)
                #pragma unroll
                for (int q = 0; q < 4; q++) acc[a][c][q] = 0.f;

        #pragma unroll 1
        for (int kt = 0; kt < 8; kt++) {
            if (kt < 7) {
                float* Wn = (kt & 1) ? Ws0 : Ws1;
                const float* src = g_Mt + (kt + 1) * 32;
                #pragma unroll
                for (int i = 0; i < 4; i++) {
                    int idx = i * 512 + t, n = idx >> 3, q = idx & 7;
                    unsigned d = (unsigned)__cvta_generic_to_shared(Wn + n * WSTR + q * 4);
                    asm volatile("cp.async.ca.shared.global [%0], [%1], 16;"
                                 :: "r"(d), "l"(src + n * 256 + q * 4));
                }
                asm volatile("cp.async.commit_group;" ::: "memory");
                asm volatile("cp.async.wait_group 1;" ::: "memory");
            } else {
                asm volatile("cp.async.wait_group 0;" ::: "memory");
            }
            __syncthreads();
            const float* W = (kt & 1) ? Ws1 : Ws0;

            #pragma unroll
            for (int ksi = 0; ksi < 2; ksi++) {
                const int kc = kt * 32 + (sH * 2 + ksi) * 8;
                unsigned a[2][4];
                #pragma unroll
                for (int mt = 0; mt < 2; mt++) {
                    const float* xp = Xs + (mb + mt * 16 + rA) * XSTR + kc + cA;
                    a[mt][0] = __float_as_uint(xp[0]);
                    a[mt][1] = __float_as_uint(xp[8 * XSTR]);
                    a[mt][2] = __float_as_uint(xp[4]);
                    a[mt][3] = __float_as_uint(xp[8 * XSTR + 4]);
                }
                #pragma unroll
                for (int nt = 0; nt < 8; nt++) {
                    const float* wp = W + (nb + nt * 8 + rA) * WSTR + (sH * 2 + ksi) * 8 + cA;
                    unsigned b0 = __float_as_uint(wp[0]);
                    unsigned b1 = __float_as_uint(wp[4]);
                    mma_tf32(acc[0][nt], a[0], b0, b1);
                    mma_tf32(acc[1][nt], a[1], b0, b1);
                }
            }
            __syncthreads();
        }

        // epilogue: sH=1 warps spill partials into overlay (Ws dead now); sH=0 adds
        if (sH == 1) {
            #pragma unroll
            for (int mt = 0; mt < 2; mt++)
                #pragma unroll
                for (int nt = 0; nt < 8; nt++) {
                    int row = mb + mt * 16 + rA;
                    int col = nb + nt * 8 + 2 * cA;
                    *(float2*)(Zp + row * XSTR + col)       = make_float2(acc[mt][nt][0], acc[mt][nt][1]);
                    *(float2*)(Zp + (row + 8) * XSTR + col) = make_float2(acc[mt][nt][2], acc[mt][nt][3]);
                }
        }
        __syncthreads();
        if (sH == 0) {
            #pragma unroll
            for (int mt = 0; mt < 2; mt++)
                #pragma unroll
                for (int nt = 0; nt < 8; nt++) {
                    int row = mb + mt * 16 + rA;
                    int col = nb + nt * 8 + 2 * cA;
                    float2 p0 = *(const float2*)(Zp + row * XSTR + col);
                    float2 p1 = *(const float2*)(Zp + (row + 8) * XSTR + col);
                    *(float2*)(Zs + row * XSTR + col) =
                        make_float2(acc[mt][nt][0] + p0.x, acc[mt][nt][1] + p0.y);
                    *(float2*)(Zs + (row + 8) * XSTR + col) =
                        make_float2(acc[mt][nt][2] + p1.x, acc[mt][nt][3] + p1.y);
                }
        }
    }
    __syncthreads();   // Zs complete; overlay free again

    // ---- GEMM 2: S[64][64] = Z @ X^T, 16 warps: (m4) x (k-quarter 4) ----
    {
        float sacc[8][4];
        #pragma unroll
        for (int c = 0; c < 8; c++)
            #pragma unroll
            for (int q = 0; q < 4; q++) sacc[c][q] = 0.f;

        const int smB = (w & 3) * 16;
        const int kq0 = (w >> 2) * 64;

        #pragma unroll 4
        for (int ks = 0; ks < 8; ks++) {
            const int kc = kq0 + ks * 8;
            unsigned a[4];
            const float* zp = Zs + (smB + rA) * XSTR + kc + cA;
            a[0] = __float_as_uint(zp[0]);
            a[1] = __float_as_uint(zp[8 * XSTR]);
            a[2] = __float_as_uint(zp[4]);
            a[3] = __float_as_uint(zp[8 * XSTR + 4]);
            #pragma unroll
            for (int nt = 0; nt < 8; nt++) {
                const float* xp = Xs + (nt * 8 + rA) * XSTR + kc + cA;
                unsigned b0 = __float_as_uint(xp[0]);
                unsigned b1 = __float_as_uint(xp[4]);
                mma_tf32(sacc[nt], a, b0, b1);
            }
        }

        float* SsH = Ssq + (w >> 2) * 64 * SSTR;
        #pragma unroll
        for (int nt = 0; nt < 8; nt++) {
            int row = smB + rA;
            int col = nt * 8 + 2 * cA;
            *(float2*)(SsH + row * SSTR + col)       = make_float2(sacc[nt][0], sacc[nt][1]);
            *(float2*)(SsH + (row + 8) * SSTR + col) = make_float2(sacc[nt][2], sacc[nt][3]);
        }
    }
    __syncthreads();

    // ---- softmax: 16-lane group per src, sum 4 k-quarter partials ----
    const float skip = attn_skip_p[0];
    const float c0 = g_c0;
    float* outEw = out + (size_t)2 * Bx * Ex * Lx;
    const int g  = j >> 4;
    const int jj = j & 15;

    #pragma unroll
    for (int it = 0; it < 2; it++) {
        const int v  = it * 32 + w * 2 + g;
        const int dst = Sd[v * 16 + jj];
        float sc = (Ssq[v * SSTR + dst]
                  + Ssq[64 * SSTR + v * SSTR + dst]
                  + Ssq[128 * SSTR + v * SSTR + dst]
                  + Ssq[192 * SSTR + v * SSTR + dst]
                  + Sa[v] + Sc[dst] + c0) * 0.0625f;
        float m = sc;
        #pragma unroll
        for (int off = 8; off > 0; off >>= 1) m = fmaxf(m, __shfl_xor_sync(~0u, m, off));
        float e = __expf(sc - m);
        float Zt = e;
        #pragma unroll
        for (int off = 8; off > 0; off >>= 1) Zt += __shfl_xor_sync(~0u, Zt, off);
        const int ge = b * Ex + v * 16 + jj;
        outEw[(size_t)ge * Lx + l] = skip * Sew[v * 16 + jj] + (1.0f - skip) * e / Zt;
    }
}

extern "C" void kernel_launch(void* const* d_in, const int* in_sizes, int n_in,
                              void* d_out, int out_size)
{
    const float* hs = (const float*)d_in[0];
    const int*   ei = (const int*)  d_in[1];
    const float* ew = (const float*)d_in[2];
    const float* Wq = (const float*)d_in[3];
    const float* bq = (const float*)d_in[4];
    const float* Wk = (const float*)d_in[5];
    const float* bk = (const float*)d_in[6];
    const float* sk = (const float*)d_in[7];
    float* out = (float*)d_out;

    precompute_kernel<<<256, 256>>>(Wq, bq, Wk, bk);

    const int smem_bytes = (64 * XSTR * 2 + 256 * WSTR * 2 + 256 + 256 + 64 + 64 + 1024 + 1024) * 4;
    cudaFuncSetAttribute(edge_learner_main,
                         cudaFuncAttributeMaxDynamicSharedMemorySize, smem_bytes);
    edge_learner_main<<<Bx * Lx, 512, smem_bytes>>>(hs, ei, ew, sk, out);
}

// round 7
// speedup vs baseline: 1.5086x; 1.5086x over previous
#include <cuda_runtime.h>
#include <cuda_fp16.h>
#include <cstdint>
#include <cstddef>

#define Bx 4
#define Vx 64
#define Ex 1024
#define Lx 1024
#define Dx 256
#define NR (Bx * Vx * Lx)          // 262144 rows

#define ASTRh 40                   // K1 A-chunk row stride (halfs)
#define BSTRh 264                  // K1 B row stride (halfs), full K resident
#define ZSTRh 136                  // K1 epilogue stage row stride (halfs)
#define HSTR  264                  // K2 Xh/Zh row stride (halfs)
#define SSTR2 68                   // K2 score row stride (floats)

__device__ __half g_Mh[256 * 256];     // Mh[n][k] = (Wq^T Wk)[k][n]
__device__ float  g_u[256];            // u[k] = sum_c Wq[c][k]*bk[c]
__device__ float  g_r[256];            // r[n] = sum_c bq[c]*Wk[c][n]
__device__ float  g_c0;                // bq . bk
__device__ __half g_Xh[(size_t)NR * 256];   // fp16 copy of hidden_states
__device__ __half g_Z [(size_t)NR * 256];   // Z = X @ M

__device__ __forceinline__ unsigned packh2(float a, float b) {
    __half2 h = __floats2half2_rn(a, b);
    return *reinterpret_cast<unsigned*>(&h);
}

__device__ __forceinline__ void mma_f16(float (&d)[4], const unsigned (&a)[4],
                                        unsigned b0, unsigned b1) {
    asm volatile("mma.sync.aligned.m16n8k16.row.col.f32.f16.f16.f32 "
                 "{%0,%1,%2,%3}, {%4,%5,%6,%7}, {%8,%9}, {%0,%1,%2,%3};"
                 : "+f"(d[0]), "+f"(d[1]), "+f"(d[2]), "+f"(d[3])
                 : "r"(a[0]), "r"(a[1]), "r"(a[2]), "r"(a[3]), "r"(b0), "r"(b1));
}

__device__ __forceinline__ void cp16(void* smem_dst, const void* gsrc) {
    unsigned d = (unsigned)__cvta_generic_to_shared(smem_dst);
    asm volatile("cp.async.ca.shared.global [%0], [%1], 16;" :: "r"(d), "l"(gsrc));
}

// ---------------- K0a: precompute M (fp16), u, r, c0 ----------------
__global__ void precompute_kernel(const float* __restrict__ Wq, const float* __restrict__ bq,
                                  const float* __restrict__ Wk, const float* __restrict__ bk)
{
    __shared__ float sWk[256];
    __shared__ float red[256];
    const int n = blockIdx.x, j = threadIdx.x;
    sWk[j] = Wk[j * 256 + n];
    __syncthreads();
    float acc = 0.f, uacc = 0.f;
    #pragma unroll 4
    for (int d = 0; d < 256; d++) {
        float wq = Wq[d * 256 + j];
        acc = fmaf(wq, sWk[d], acc);
        if (n == 0) uacc = fmaf(wq, __ldg(bk + d), uacc);
    }
    g_Mh[n * 256 + j] = __float2half_rn(acc);   // Mh[n][k=j] = M[k][n]
    if (n == 0) g_u[j] = uacc;
    red[j] = bq[j] * sWk[j];
    __syncthreads();
    for (int s = 128; s > 0; s >>= 1) { if (j < s) red[j] += red[j + s]; __syncthreads(); }
    if (j == 0) g_r[n] = red[0];
    if (n == 0) {
        red[j] = bq[j] * __ldg(bk + j);
        __syncthreads();
        for (int s = 128; s > 0; s >>= 1) { if (j < s) red[j] += red[j + s]; __syncthreads(); }
        if (j == 0) g_c0 = red[0];
    }
}

// ---------------- K0b: hs fp32 -> fp16 ----------------
__global__ __launch_bounds__(256) void convert_kernel(const float* __restrict__ hs)
{
    size_t i = ((size_t)blockIdx.x * 256 + threadIdx.x) * 8;
    float4 f0 = *(const float4*)(hs + i);
    float4 f1 = *(const float4*)(hs + i + 4);
    uint4 o;
    o.x = packh2(f0.x, f0.y); o.y = packh2(f0.z, f0.w);
    o.z = packh2(f1.x, f1.y); o.w = packh2(f1.z, f1.w);
    *(uint4*)(g_Xh + i) = o;
}

// ---------------- K1: Z[262144][256] = Xh @ Mh^T, fp16 mma ----------------
// grid (2048, 2): 128-row tile x 128-n half. 256 threads = 4m x 2n warps (m32 x n64).
__global__ __launch_bounds__(256, 2) void gemm1_kernel()
{
    extern __shared__ __half sh[];
    __half* As  = sh;                        // 2 x 128 x ASTRh
    __half* Bs  = sh + 2 * 128 * ASTRh;      // 128 x BSTRh
    __half* Zst = Bs;                        // epilogue overlay (B dead)

    const int t = threadIdx.x, w = t >> 5, j = t & 31;
    const int r0 = blockIdx.x * 128;
    const int n0 = blockIdx.y * 128;
    const int rA = j >> 2, cA = j & 3;
    const int mb = (w & 3) * 32, nb = (w >> 2) * 64;

    // stage B (full K, resident): 128 n-rows x 256 k halfs
    #pragma unroll
    for (int i = 0; i < 16; i++) {
        int idx = i * 256 + t, nl = idx >> 5, q = idx & 31;
        cp16(Bs + nl * BSTRh + q * 8, g_Mh + (n0 + nl) * 256 + q * 8);
    }
    asm volatile("cp.async.commit_group;" ::: "memory");
    // stage A chunk 0
    #pragma unroll
    for (int i = 0; i < 2; i++) {
        int idx = i * 256 + t, row = idx >> 2, q = idx & 3;
        cp16(As + row * ASTRh + q * 8, g_Xh + (size_t)(r0 + row) * 256 + q * 8);
    }
    asm volatile("cp.async.commit_group;" ::: "memory");

    float acc[2][8][4];
    #pragma unroll
    for (int a = 0; a < 2; a++)
        #pragma unroll
        for (int c = 0; c < 8; c++)
            #pragma unroll
            for (int q = 0; q < 4; q++) acc[a][c][q] = 0.f;

    #pragma unroll 1
    for (int kt = 0; kt < 8; kt++) {
        if (kt < 7) {
            __half* Ab = As + ((kt + 1) & 1) * 128 * ASTRh;
            #pragma unroll
            for (int i = 0; i < 2; i++) {
                int idx = i * 256 + t, row = idx >> 2, q = idx & 3;
                cp16(Ab + row * ASTRh + q * 8,
                     g_Xh + (size_t)(r0 + row) * 256 + (kt + 1) * 32 + q * 8);
            }
            asm volatile("cp.async.commit_group;" ::: "memory");
            asm volatile("cp.async.wait_group 1;" ::: "memory");
        } else {
            asm volatile("cp.async.wait_group 0;" ::: "memory");
        }
        __syncthreads();
        const __half* A = As + (kt & 1) * 128 * ASTRh;

        #pragma unroll
        for (int ks = 0; ks < 2; ks++) {
            const int kcA = ks * 16 + 2 * cA;
            const int kcB = kt * 32 + ks * 16 + 2 * cA;
            unsigned a[2][4];
            #pragma unroll
            for (int mt = 0; mt < 2; mt++) {
                const __half* ap = A + (mb + mt * 16 + rA) * ASTRh + kcA;
                a[mt][0] = *(const unsigned*)(ap);
                a[mt][1] = *(const unsigned*)(ap + 8 * ASTRh);
                a[mt][2] = *(const unsigned*)(ap + 8);
                a[mt][3] = *(const unsigned*)(ap + 8 * ASTRh + 8);
            }
            #pragma unroll
            for (int nt = 0; nt < 8; nt++) {
                const __half* bp = Bs + (nb + nt * 8 + rA) * BSTRh + kcB;
                unsigned b0 = *(const unsigned*)(bp);
                unsigned b1 = *(const unsigned*)(bp + 8);
                mma_f16(acc[0][nt], a[0], b0, b1);
                mma_f16(acc[1][nt], a[1], b0, b1);
            }
        }
        __syncthreads();
    }

    // epilogue: pack fp16 into stage (overlay on B), then coalesced STG.128
    #pragma unroll
    for (int mt = 0; mt < 2; mt++)
        #pragma unroll
        for (int nt = 0; nt < 8; nt++) {
            int row = mb + mt * 16 + rA;
            int col = nb + nt * 8 + 2 * cA;
            *(unsigned*)(Zst + row * ZSTRh + col)       = packh2(acc[mt][nt][0], acc[mt][nt][1]);
            *(unsigned*)(Zst + (row + 8) * ZSTRh + col) = packh2(acc[mt][nt][2], acc[mt][nt][3]);
        }
    __syncthreads();
    #pragma unroll
    for (int i = 0; i < 8; i++) {
        int idx = i * 256 + t, row = idx >> 4, q = idx & 15;
        *(uint4*)(g_Z + (size_t)(r0 + row) * 256 + n0 + q * 8) =
            *(const uint4*)(Zst + row * ZSTRh + q * 8);
    }
}

// ---------------- K2: per (b,l): S = Z.X^T, softmax over 16 nbrs, outputs ----------------
__global__ __launch_bounds__(256, 2)
void attn_kernel(const int*   __restrict__ edge_index,
                 const float* __restrict__ edge_weight,
                 const float* __restrict__ attn_skip_p,
                 float* __restrict__ out)
{
    extern __shared__ char smraw[];
    __half* Xh = (__half*)smraw;                       // 64 x HSTR
    __half* Zh = Xh + 64 * HSTR;                       // 64 x HSTR
    float*  Ss = (float*)(Zh + 64 * HSTR);             // 2 x 64 x SSTR2
    float*  Sa = Ss + 2 * 64 * SSTR2;                  // 64
    float*  Sc = Sa + 64;                              // 64
    int*    Sd = (int*)(Sc + 64);                      // 1024
    float*  Sew = (float*)(Sd + 1024);                 // 1024

    const int bx = blockIdx.x;
    const int b = bx >> 10, l = bx & 1023;
    const int t = threadIdx.x, w = t >> 5, j = t & 31;
    const int rA = j >> 2, cA = j & 3;

    // stage Xh, Zh slices (64 rows x 256 halfs each) via cp.async
    #pragma unroll
    for (int i = 0; i < 8; i++) {
        int idx = i * 256 + t, v = idx >> 5, q = idx & 31;
        size_t rowoff = ((size_t)(b * Vx + v) * Lx + l) * 256;
        cp16(Xh + v * HSTR + q * 8, g_Xh + rowoff + q * 8);
        cp16(Zh + v * HSTR + q * 8, g_Z  + rowoff + q * 8);
    }
    asm volatile("cp.async.commit_group;" ::: "memory");

    // ei output fill (overlapped with cp.async)
    {
        const int base = bx * 2048;
        #pragma unroll
        for (int r = 0; r < 8; r++) {
            int idx = base + r * 256 + t;
            out[idx] = (float)edge_index[idx >> 10];
        }
    }
    // dst + edge weights
    {
        const int*   dsts = edge_index + Bx * Ex + b * Ex;
        const float* ews  = edge_weight + b * Ex;
        #pragma unroll
        for (int i = 0; i < 4; i++) {
            Sd[i * 256 + t]  = dsts[i * 256 + t];
            Sew[i * 256 + t] = ews[i * 256 + t];
        }
    }
    asm volatile("cp.async.wait_group 0;" ::: "memory");
    __syncthreads();

    // bias dots: Sa[v] = x_v.u , Sc[v] = r.x_v  (x from Xh, u/r fp32 from global)
    {
        const float4 u0 = __ldg((const float4*)(g_u) + j);        // g_u[4j..4j+3]
        const float4 u1 = __ldg((const float4*)(g_u) + 32 + j);   // g_u[128+4j..]
        const float4 r0 = __ldg((const float4*)(g_r) + j);
        const float4 r1 = __ldg((const float4*)(g_r) + 32 + j);
        #pragma unroll
        for (int s = 0; s < 8; s++) {
            int v = w * 8 + s;
            float2 xa0 = __half22float2(*(const __half2*)(Xh + v * HSTR + 4 * j));
            float2 xa1 = __half22float2(*(const __half2*)(Xh + v * HSTR + 4 * j + 2));
            float2 xb0 = __half22float2(*(const __half2*)(Xh + v * HSTR + 128 + 4 * j));
            float2 xb1 = __half22float2(*(const __half2*)(Xh + v * HSTR + 128 + 4 * j + 2));
            float pa = xa0.x*u0.x + xa0.y*u0.y + xa1.x*u0.z + xa1.y*u0.w
                     + xb0.x*u1.x + xb0.y*u1.y + xb1.x*u1.z + xb1.y*u1.w;
            float pc = xa0.x*r0.x + xa0.y*r0.y + xa1.x*r0.z + xa1.y*r0.w
                     + xb0.x*r1.x + xb0.y*r1.y + xb1.x*r1.z + xb1.y*r1.w;
            #pragma unroll
            for (int off = 16; off > 0; off >>= 1) {
                pa += __shfl_xor_sync(~0u, pa, off);
                pc += __shfl_xor_sync(~0u, pc, off);
            }
            if (j == 0) { Sa[v] = pa; Sc[v] = pc; }
        }
    }

    // GEMM2: S[64][64] = Zh @ Xh^T ; 8 warps = 4 m-tiles(m16) x 2 k-halves(k128)
    {
        float sacc[8][4];
        #pragma unroll
        for (int c = 0; c < 8; c++)
            #pragma unroll
            for (int q = 0; q < 4; q++) sacc[c][q] = 0.f;

        const int m0 = (w & 3) * 16;
        const int kh = w >> 2;

        #pragma unroll
        for (int ks = 0; ks < 8; ks++) {
            const int kc = kh * 128 + ks * 16 + 2 * cA;
            unsigned a[4];
            const __half* ap = Zh + (m0 + rA) * HSTR + kc;
            a[0] = *(const unsigned*)(ap);
            a[1] = *(const unsigned*)(ap + 8 * HSTR);
            a[2] = *(const unsigned*)(ap + 8);
            a[3] = *(const unsigned*)(ap + 8 * HSTR + 8);
            #pragma unroll
            for (int nt = 0; nt < 8; nt++) {
                const __half* bp = Xh + (nt * 8 + rA) * HSTR + kc;
                unsigned b0 = *(const unsigned*)(bp);
                unsigned b1 = *(const unsigned*)(bp + 8);
                mma_f16(sacc[nt], a, b0, b1);
            }
        }

        float* SsH = Ss + kh * 64 * SSTR2;
        #pragma unroll
        for (int nt = 0; nt < 8; nt++) {
            int row = m0 + rA;
            int col = nt * 8 + 2 * cA;
            *(float2*)(SsH + row * SSTR2 + col)       = make_float2(sacc[nt][0], sacc[nt][1]);
            *(float2*)(SsH + (row + 8) * SSTR2 + col) = make_float2(sacc[nt][2], sacc[nt][3]);
        }
    }
    __syncthreads();

    // softmax: 16-lane group per src
    const float skip = attn_skip_p[0];
    const float c0 = g_c0;
    float* outEw = out + (size_t)2 * Bx * Ex * Lx;
    const int g  = j >> 4;
    const int jj = j & 15;

    #pragma unroll
    for (int it = 0; it < 4; it++) {
        const int v  = it * 16 + w * 2 + g;
        const int dst = Sd[v * 16 + jj];
        float sc = (Ss[v * SSTR2 + dst] + Ss[64 * SSTR2 + v * SSTR2 + dst]
                    + Sa[v] + Sc[dst] + c0) * 0.0625f;
        float m = sc;
        #pragma unroll
        for (int off = 8; off > 0; off >>= 1) m = fmaxf(m, __shfl_xor_sync(~0u, m, off));
        float e = __expf(sc - m);
        float Zt = e;
        #pragma unroll
        for (int off = 8; off > 0; off >>= 1) Zt += __shfl_xor_sync(~0u, Zt, off);
        const int ge = b * Ex + v * 16 + jj;
        outEw[(size_t)ge * Lx + l] = skip * Sew[v * 16 + jj] + (1.0f - skip) * e / Zt;
    }
}

extern "C" void kernel_launch(void* const* d_in, const int* in_sizes, int n_in,
                              void* d_out, int out_size)
{
    const float* hs = (const float*)d_in[0];
    const int*   ei = (const int*)  d_in[1];
    const float* ew = (const float*)d_in[2];
    const float* Wq = (const float*)d_in[3];
    const float* bq = (const float*)d_in[4];
    const float* Wk = (const float*)d_in[5];
    const float* bk = (const float*)d_in[6];
    const float* sk = (const float*)d_in[7];
    float* out = (float*)d_out;

    precompute_kernel<<<256, 256>>>(Wq, bq, Wk, bk);
    convert_kernel<<<NR * 256 / (256 * 8), 256>>>(hs);

    const int smem1 = (2 * 128 * ASTRh + 128 * BSTRh) * 2;                 // 88064 B
    cudaFuncSetAttribute(gemm1_kernel, cudaFuncAttributeMaxDynamicSharedMemorySize, smem1);
    gemm1_kernel<<<dim3(2048, 2), 256, smem1>>>();

    const int smem2 = 64 * HSTR * 2 * 2 + (2 * 64 * SSTR2 + 64 + 64) * 4 + 1024 * 4 * 2;  // 111104 B
    cudaFuncSetAttribute(attn_kernel, cudaFuncAttributeMaxDynamicSharedMemorySize, smem2);
    attn_kernel<<<Bx * Lx, 256, smem2>>>(ei, ew, sk, out);
}

// round 9
// speedup vs baseline: 1.5861x; 1.0513x over previous
#include <cuda_runtime.h>
#include <cuda_fp16.h>
#include <cstdint>
#include <cstddef>

#define Bx 4
#define Vx 64
#define Ex 1024
#define Lx 1024
#define NR (Bx * Vx * Lx)          // 262144 rows

#define F32STR 36                  // gemm1 fp32 A stage row stride (floats)
#define ASTRh  40                  // gemm1 fp16 A row stride (halfs)
#define BSTRh  264                 // gemm1 B row stride (halfs)
#define ZSTRh  136                 // gemm1 epilogue stage row stride (halfs)
#define HSTR   264                 // attn Xh/Zh row stride (halfs)
#define BSS    36                  // attn score row stride (floats)

__device__ __align__(16) __half g_Mh[256 * 256];   // Mh[n][k] = (Wq^T Wk)[k][n]
__device__ __align__(16) float  g_r[256];          // r[n] = sum_c bq[c]*Wk[c][n]
__device__ __align__(16) __half g_Xh[(size_t)NR * 256];   // fp16 hidden_states
__device__ __align__(16) __half g_Z [(size_t)NR * 256];   // Z = X @ M + r  (r folded)

__device__ __forceinline__ unsigned packh2(float a, float b) {
    __half2 h = __floats2half2_rn(a, b);
    return *reinterpret_cast<unsigned*>(&h);
}

__device__ __forceinline__ void mma_f16(float (&d)[4], const unsigned (&a)[4],
                                        unsigned b0, unsigned b1) {
    asm volatile("mma.sync.aligned.m16n8k16.row.col.f32.f16.f16.f32 "
                 "{%0,%1,%2,%3}, {%4,%5,%6,%7}, {%8,%9}, {%0,%1,%2,%3};"
                 : "+f"(d[0]), "+f"(d[1]), "+f"(d[2]), "+f"(d[3])
                 : "r"(a[0]), "r"(a[1]), "r"(a[2]), "r"(a[3]), "r"(b0), "r"(b1));
}

__device__ __forceinline__ void cp16(void* smem_dst, const void* gsrc) {
    unsigned d = (unsigned)__cvta_generic_to_shared(smem_dst);
    asm volatile("cp.async.ca.shared.global [%0], [%1], 16;" :: "r"(d), "l"(gsrc));
}

__device__ __forceinline__ void ldsm_x4(unsigned &r0, unsigned &r1, unsigned &r2,
                                        unsigned &r3, const void* p) {
    unsigned a = (unsigned)__cvta_generic_to_shared(p);
    asm volatile("ldmatrix.sync.aligned.m8n8.x4.shared.b16 {%0,%1,%2,%3}, [%4];"
                 : "=r"(r0), "=r"(r1), "=r"(r2), "=r"(r3) : "r"(a));
}

// ---------------- K0: precompute M (fp16) and r ----------------
__global__ void precompute_kernel(const float* __restrict__ Wq, const float* __restrict__ bq,
                                  const float* __restrict__ Wk, const float* __restrict__ bk)
{
    __shared__ float sWk[256];
    __shared__ float red[256];
    const int n = blockIdx.x, j = threadIdx.x;
    sWk[j] = Wk[j * 256 + n];
    __syncthreads();
    float acc = 0.f;
    #pragma unroll 4
    for (int d = 0; d < 256; d++)
        acc = fmaf(Wq[d * 256 + j], sWk[d], acc);
    g_Mh[n * 256 + j] = __float2half_rn(acc);   // Mh[n][k=j] = M[k][n]
    red[j] = bq[j] * sWk[j];
    __syncthreads();
    for (int s = 128; s > 0; s >>= 1) { if (j < s) red[j] += red[j + s]; __syncthreads(); }
    if (j == 0) g_r[n] = red[0];
}

// ---------------- K1: fused convert + GEMM  Z = Xh @ Mh^T + r ----------------
// grid (2048, 2): 128-row tile x 128-n half. 256 threads = 4m x 2n warps (m32 x n64).
__global__ __launch_bounds__(256, 2) void gemm1_kernel(const float* __restrict__ hs)
{
    extern __shared__ char smraw1[];
    float*  F   = (float*)smraw1;                        // 128 x F32STR fp32 stage
    __half* Ah  = (__half*)(F + 128 * F32STR);           // 2 x 128 x ASTRh
    __half* Bs  = Ah + 2 * 128 * ASTRh;                  // 128 x BSTRh
    float*  Sr  = (float*)(Bs + 128 * BSTRh);            // 128
    __half* Zst = Bs;                                    // epilogue overlay (B dead)

    const int t = threadIdx.x, w = t >> 5, j = t & 31;
    const int r0 = blockIdx.x * 128;
    const int n0 = blockIdx.y * 128;
    const int rA = j >> 2, cA = j & 3;
    const int mb = (w & 3) * 32, nb = (w >> 2) * 64;

    // stage B (128 n-rows x 256 k) + r
    #pragma unroll
    for (int i = 0; i < 16; i++) {
        int idx = i * 256 + t, nl = idx >> 5, q = idx & 31;
        cp16(Bs + nl * BSTRh + q * 8, g_Mh + (n0 + nl) * 256 + q * 8);
    }
    if (t < 32) ((float4*)Sr)[t] = __ldg((const float4*)(g_r + n0) + t);
    // stage fp32 A chunk 0
    #pragma unroll
    for (int i = 0; i < 4; i++) {
        int idx = i * 256 + t, row = idx >> 3, q = idx & 7;
        cp16(F + row * F32STR + q * 4, hs + (size_t)(r0 + row) * 256 + q * 4);
    }
    asm volatile("cp.async.commit_group;" ::: "memory");

    float acc[2][8][4];
    #pragma unroll
    for (int a = 0; a < 2; a++)
        #pragma unroll
        for (int c = 0; c < 8; c++)
            #pragma unroll
            for (int q = 0; q < 4; q++) acc[a][c][q] = 0.f;

    const int cvrow = t >> 1, cvh = t & 1;       // convert: 2 threads per row

    #pragma unroll 1
    for (int kt = 0; kt < 8; kt++) {
        asm volatile("cp.async.wait_group 0;" ::: "memory");
        __syncthreads();
        // convert fp32 chunk -> fp16 Ah[kt&1], and write g_Xh (only n-half 0 writes)
        __half* A = Ah + (kt & 1) * 128 * ASTRh;
        {
            const float* fp = F + cvrow * F32STR + cvh * 16;
            float4 f0 = *(const float4*)(fp);
            float4 f1 = *(const float4*)(fp + 4);
            float4 f2 = *(const float4*)(fp + 8);
            float4 f3 = *(const float4*)(fp + 12);
            uint4 o0, o1;
            o0.x = packh2(f0.x, f0.y); o0.y = packh2(f0.z, f0.w);
            o0.z = packh2(f1.x, f1.y); o0.w = packh2(f1.z, f1.w);
            o1.x = packh2(f2.x, f2.y); o1.y = packh2(f2.z, f2.w);
            o1.z = packh2(f3.x, f3.y); o1.w = packh2(f3.z, f3.w);
            __half* ap = A + cvrow * ASTRh + cvh * 16;
            *(uint4*)(ap) = o0;
            *(uint4*)(ap + 8) = o1;
            if (blockIdx.y == 0) {
                __half* gx = g_Xh + (size_t)(r0 + cvrow) * 256 + kt * 32 + cvh * 16;
                *(uint4*)(gx) = o0;
                *(uint4*)(gx + 8) = o1;
            }
        }
        __syncthreads();
        if (kt < 7) {                             // prefetch next fp32 chunk
            #pragma unroll
            for (int i = 0; i < 4; i++) {
                int idx = i * 256 + t, row = idx >> 3, q = idx & 7;
                cp16(F + row * F32STR + q * 4,
                     hs + (size_t)(r0 + row) * 256 + (kt + 1) * 32 + q * 4);
            }
            asm volatile("cp.async.commit_group;" ::: "memory");
        }

        #pragma unroll
        for (int ks = 0; ks < 2; ks++) {
            const int kcB = kt * 32 + ks * 16;
            unsigned a[2][4];
            #pragma unroll
            for (int mt = 0; mt < 2; mt++) {
                int arow = mb + mt * 16 + (j & 7) + ((j >> 3) & 1) * 8;
                ldsm_x4(a[mt][0], a[mt][1], a[mt][2], a[mt][3],
                        A + arow * ASTRh + ks * 16 + (j >> 4) * 8);
            }
            #pragma unroll
            for (int p = 0; p < 4; p++) {
                unsigned b0, b1, b2, b3;
                int brow = nb + p * 16 + (j >> 4) * 8 + (j & 7);
                ldsm_x4(b0, b1, b2, b3,
                        Bs + brow * BSTRh + kcB + ((j >> 3) & 1) * 8);
                mma_f16(acc[0][2 * p],     a[0], b0, b1);
                mma_f16(acc[1][2 * p],     a[1], b0, b1);
                mma_f16(acc[0][2 * p + 1], a[0], b2, b3);
                mma_f16(acc[1][2 * p + 1], a[1], b2, b3);
            }
        }
    }
    __syncthreads();

    // epilogue: add r, pack fp16 into stage (overlay on B), coalesced STG.128
    #pragma unroll
    for (int mt = 0; mt < 2; mt++)
        #pragma unroll
        for (int nt = 0; nt < 8; nt++) {
            int row = mb + mt * 16 + rA;
            int col = nb + nt * 8 + 2 * cA;
            float rc0 = Sr[col], rc1 = Sr[col + 1];
            *(unsigned*)(Zst + row * ZSTRh + col) =
                packh2(acc[mt][nt][0] + rc0, acc[mt][nt][1] + rc1);
            *(unsigned*)(Zst + (row + 8) * ZSTRh + col) =
                packh2(acc[mt][nt][2] + rc0, acc[mt][nt][3] + rc1);
        }
    __syncthreads();
    #pragma unroll
    for (int i = 0; i < 8; i++) {
        int idx = i * 256 + t, row = idx >> 4, q = idx & 15;
        *(uint4*)(g_Z + (size_t)(r0 + row) * 256 + n0 + q * 8) =
            *(const uint4*)(Zst + row * ZSTRh + q * 8);
    }
}

// ---------------- K2: per (b,l): banded S = (Z+r).X^T, softmax, outputs ----------------
__global__ __launch_bounds__(256, 2)
void attn_kernel(const int*   __restrict__ edge_index,
                 const float* __restrict__ edge_weight,
                 const float* __restrict__ attn_skip_p,
                 float* __restrict__ out)
{
    extern __shared__ char smraw[];
    __half* Xh = (__half*)smraw;                       // 64 x HSTR
    __half* Zh = Xh + 64 * HSTR;                       // 64 x HSTR
    float*  Ss = (float*)(Zh + 64 * HSTR);             // 2 x 64 x BSS
    int*    Sd = (int*)(Ss + 2 * 64 * BSS);            // 1024
    float*  Sew = (float*)(Sd + 1024);                 // 1024

    const int bx = blockIdx.x;
    const int b = bx >> 10, l = bx & 1023;
    const int t = threadIdx.x, w = t >> 5, j = t & 31;
    const int rA = j >> 2, cA = j & 3;

    // stage Xh, Zh slices via cp.async
    #pragma unroll
    for (int i = 0; i < 8; i++) {
        int idx = i * 256 + t, v = idx >> 5, q = idx & 31;
        size_t rowoff = ((size_t)(b * Vx + v) * Lx + l) * 256;
        cp16(Xh + v * HSTR + q * 8, g_Xh + rowoff + q * 8);
        cp16(Zh + v * HSTR + q * 8, g_Z  + rowoff + q * 8);
    }
    asm volatile("cp.async.commit_group;" ::: "memory");

    // ei output fill (overlaps the cp.async)
    {
        const int base = bx * 2048;
        #pragma unroll
        for (int r = 0; r < 8; r++) {
            int idx = base + r * 256 + t;
            out[idx] = (float)edge_index[idx >> 10];
        }
    }
    // dst + edge weights
    {
        const int*   dsts = edge_index + Bx * Ex + b * Ex;
        const float* ews  = edge_weight + b * Ex;
        #pragma unroll
        for (int i = 0; i < 4; i++) {
            Sd[i * 256 + t]  = dsts[i * 256 + t];
            Sew[i * 256 + t] = ews[i * 256 + t];
        }
    }
    asm volatile("cp.async.wait_group 0;" ::: "memory");
    __syncthreads();

    // banded GEMM: S[64][32] = Zh @ Xh[band]^T
    // 8 warps: m-tile (w&3)*16, k-half (w>>2)*128. n-cols = rows (v0+1 .. v0+32) mod 64.
    {
        float sacc[4][4];
        #pragma unroll
        for (int c = 0; c < 4; c++)
            #pragma unroll
            for (int q = 0; q < 4; q++) sacc[c][q] = 0.f;

        const int m0 = (w & 3) * 16;
        const int kh = w >> 2;

        #pragma unroll
        for (int ks = 0; ks < 8; ks++) {
            const int kc = kh * 128 + ks * 16;
            unsigned a[4];
            {
                int arow = m0 + (j & 7) + ((j >> 3) & 1) * 8;
                ldsm_x4(a[0], a[1], a[2], a[3],
                        Zh + arow * HSTR + kc + (j >> 4) * 8);
            }
            #pragma unroll
            for (int p = 0; p < 2; p++) {
                unsigned b0, b1, b2, b3;
                int nrow = (m0 + 1 + (2 * p + (j >> 4)) * 8 + (j & 7)) & 63;
                ldsm_x4(b0, b1, b2, b3,
                        Xh + nrow * HSTR + kc + ((j >> 3) & 1) * 8);
                mma_f16(sacc[2 * p],     a, b0, b1);
                mma_f16(sacc[2 * p + 1], a, b2, b3);
            }
        }

        float* SsH = Ss + kh * 64 * BSS;
        #pragma unroll
        for (int nt = 0; nt < 4; nt++) {
            int row = m0 + rA;
            int col = nt * 8 + 2 * cA;
            *(float2*)(SsH + row * BSS + col)       = make_float2(sacc[nt][0], sacc[nt][1]);
            *(float2*)(SsH + (row + 8) * BSS + col) = make_float2(sacc[nt][2], sacc[nt][3]);
        }
    }
    __syncthreads();

    // softmax over each src's 16 neighbors; 16-lane group per src
    const float skip = attn_skip_p[0];
    float* outEw = out + (size_t)2 * Bx * Ex * Lx;
    const int g  = j >> 4;
    const int jj = j & 15;

    #pragma unroll
    for (int it = 0; it < 4; it++) {
        const int v  = it * 16 + w * 2 + g;
        const int dst = Sd[v * 16 + jj];
        const int col = (dst - (v & ~15) - 1) & 63;        // in [0,32)
        float sc = (Ss[v * BSS + col] + Ss[64 * BSS + v * BSS + col]) * 0.0625f;
        float m = sc;
        #pragma unroll
        for (int off = 8; off > 0; off >>= 1) m = fmaxf(m, __shfl_xor_sync(~0u, m, off));
        float e = __expf(sc - m);
        float Zt = e;
        #pragma unroll
        for (int off = 8; off > 0; off >>= 1) Zt += __shfl_xor_sync(~0u, Zt, off);
        const int ge = b * Ex + v * 16 + jj;
        outEw[(size_t)ge * Lx + l] = skip * Sew[v * 16 + jj] + (1.0f - skip) * e / Zt;
    }
}

extern "C" void kernel_launch(void* const* d_in, const int* in_sizes, int n_in,
                              void* d_out, int out_size)
{
    const float* hs = (const float*)d_in[0];
    const int*   ei = (const int*)  d_in[1];
    const float* ew = (const float*)d_in[2];
    const float* Wq = (const float*)d_in[3];
    const float* bq = (const float*)d_in[4];
    const float* Wk = (const float*)d_in[5];
    const float* bk = (const float*)d_in[6];
    const float* sk = (const float*)d_in[7];
    float* out = (float*)d_out;

    precompute_kernel<<<256, 256>>>(Wq, bq, Wk, bk);

    const int smem1 = 128 * F32STR * 4 + 2 * 128 * ASTRh * 2 + 128 * BSTRh * 2 + 128 * 4;
    cudaFuncSetAttribute(gemm1_kernel, cudaFuncAttributeMaxDynamicSharedMemorySize, smem1);
    gemm1_kernel<<<dim3(2048, 2), 256, smem1>>>(hs);

    const int smem2 = 64 * HSTR * 2 * 2 + 2 * 64 * BSS * 4 + 1024 * 4 * 2;
    cudaFuncSetAttribute(attn_kernel, cudaFuncAttributeMaxDynamicSharedMemorySize, smem2);
    attn_kernel<<<Bx * Lx, 256, smem2>>>(ei, ew, sk, out);
}